// round 16
// baseline (speedup 1.0000x reference)
#include <cuda_runtime.h>
#include <cuda_bf16.h>
#include <cub/cub.cuh>

// Problem shape (TokenSelector_83708912599683)
#define BB 32
#define SS 65536
#define DD 32
#define HH 16

// Radix-select parameters
#define NBUCK 4096           // 12-bit buckets of score float bits
#define BSHIFT 18            // bucket = score_bits >> 18
#define CAP_PB 16384         // per-batch candidate capacity (exp ~8k worst)
#define CAP (BB * CAP_PB)    // 524288 total sorted items

// Scratch: __device__ globals (runtime allocation is forbidden)
__device__ unsigned long long g_keys64[CAP];
__device__ unsigned long long g_keys64_out[CAP];
__device__ unsigned int      g_vals[CAP];
__device__ unsigned int      g_vals_out[CAP];
__device__ unsigned int      g_hist[BB * NBUCK];
__device__ unsigned int      g_thresh[BB];
__device__ unsigned int      g_cnt[BB];
__device__ unsigned int      g_start[BB];
__device__ unsigned char     g_temp[16 * 1024 * 1024];

// ===== FROZEN numerics (bit-matched to reference, R13 PASS) =====
__device__ __forceinline__ float ref_expf(float x0) {
    float x = fminf(x0, 88.8f);
    x = fmaxf(x, -88.8f);
    float fx = floorf(__fadd_rn(__fmul_rn(x, 1.44269504088896341f), 0.5f));
    float tmp = __fmul_rn(fx, 0.693359375f);
    float zc  = __fmul_rn(fx, -2.12194440e-4f);
    x = __fsub_rn(x, tmp);
    x = __fsub_rn(x, zc);
    float z = __fmul_rn(x, x);
    float y = 1.9875691500E-4f;
    y = __fadd_rn(__fmul_rn(y, x), 1.3981999507E-3f);
    y = __fadd_rn(__fmul_rn(y, x), 8.3334519073E-3f);
    y = __fadd_rn(__fmul_rn(y, x), 4.1665795894E-2f);
    y = __fadd_rn(__fmul_rn(y, x), 1.6666665459E-1f);
    y = __fadd_rn(__fmul_rn(y, x), 5.0000001201E-1f);
    y = fmaf(y, z, x);                   // fused (frozen)
    y = __fadd_rn(y, 1.0f);
    int n = (int)fx;
    float p2n = __int_as_float((n + 127) << 23);
    return __fmul_rn(y, p2n);
}

// One thread per (b, s). Arithmetic FROZEN (R13).
__global__ void score_kernel(const float* __restrict__ emb,
                             const float* __restrict__ W1,
                             const float* __restrict__ b1,
                             const float* __restrict__ W2,
                             const float* __restrict__ b2,
                             float* __restrict__ scores_out) {
    __shared__ float sW1[DD * HH];
    __shared__ float sb1[HH];
    __shared__ float sW2[HH];
    __shared__ float sb2;

    int t = threadIdx.x;
    for (int idx = t; idx < DD * HH; idx += blockDim.x) sW1[idx] = W1[idx];
    if (t < HH) { sb1[t] = b1[t]; sW2[t] = W2[t]; }
    if (t == 0) sb2 = b2[0];
    __syncthreads();

    long long i = (long long)blockIdx.x * blockDim.x + t;
    if (i >= (long long)BB * SS) return;

    const float4* row = (const float4*)(emb + i * DD);
    float h[HH];
#pragma unroll
    for (int j = 0; j < HH; j++) h[j] = 0.0f;

#pragma unroll
    for (int q = 0; q < DD / 4; q++) {
        float4 x = row[q];
#pragma unroll
        for (int j = 0; j < HH; j++) {
            h[j] = fmaf(x.x, sW1[(4 * q + 0) * HH + j], h[j]);
            h[j] = fmaf(x.y, sW1[(4 * q + 1) * HH + j], h[j]);
            h[j] = fmaf(x.z, sW1[(4 * q + 2) * HH + j], h[j]);
            h[j] = fmaf(x.w, sW1[(4 * q + 3) * HH + j], h[j]);
        }
    }

    float z = 0.0f;
#pragma unroll
    for (int j = 0; j < HH; j++) {
        float a = fmaxf(__fadd_rn(h[j], sb1[j]), 0.0f);
        z = fmaf(a, sW2[j], z);
    }
    z = __fadd_rn(z, sb2);

    float e  = ref_expf(-z);
    float sc = __fdiv_rn(1.0f, __fadd_rn(1.0f, e));

    scores_out[i] = sc;
}

// 12-bit histogram of score bits per batch. grid=256, 8 blocks per batch.
__global__ void hist_kernel(const float* __restrict__ scores) {
    __shared__ unsigned int sh[NBUCK];
    for (int i = threadIdx.x; i < NBUCK; i += blockDim.x) sh[i] = 0;
    __syncthreads();

    int batch = blockIdx.x >> 3;
    long long base = (long long)blockIdx.x * 8192;
#pragma unroll
    for (int j = 0; j < 32; j++) {
        unsigned int bits = __float_as_uint(scores[base + threadIdx.x + j * 256]);
        atomicAdd(&sh[bits >> BSHIFT], 1u);
    }
    __syncthreads();
    for (int i = threadIdx.x; i < NBUCK; i += blockDim.x)
        if (sh[i]) atomicAdd(&g_hist[batch * NBUCK + i], sh[i]);
}

// Per-batch descending scan: threshold bucket T with
// count(bucket > T) < k <= count(bucket >= T). One block per batch.
__global__ void scan_kernel(int k) {
    __shared__ unsigned int part[256];
    int b = blockIdx.x;
    int t = threadIdx.x;
    unsigned int local[16];
    unsigned int sum = 0;
#pragma unroll
    for (int j = 0; j < 16; j++) {
        local[j] = g_hist[b * NBUCK + (NBUCK - 1 - 16 * t - j)];
        sum += local[j];
    }
    part[t] = sum;
    __syncthreads();
    for (int off = 1; off < 256; off <<= 1) {
        unsigned int v = (t >= off) ? part[t - off] : 0u;
        __syncthreads();
        part[t] += v;
        __syncthreads();
    }
    unsigned int pre = (t == 0) ? 0u : part[t - 1];
    if (pre < (unsigned int)k && part[t] >= (unsigned int)k) {
        unsigned int cum = pre;
#pragma unroll
        for (int j = 0; j < 16; j++) {
            cum += local[j];
            if (cum >= (unsigned int)k) {
                g_thresh[b] = NBUCK - 1 - 16 * t - j;
                break;
            }
        }
    }
}

// Compaction with EXPLICIT tie-break in the key (arrival order is scrambled
// by atomics, so stability can't be relied on):
//   key = batch(5b @48) | score_bits(32b @16) | ~index(16b @0)
// Descending sort => score desc, then index ASC for exact ties (jax top_k).
__global__ void compact_kernel(const float* __restrict__ scores) {
    long long i = (long long)blockIdx.x * blockDim.x + threadIdx.x;
    if (i >= (long long)BB * SS) return;
    int b = (int)(i >> 16);
    unsigned int s = (unsigned int)(i & (SS - 1));
    unsigned int bits = __float_as_uint(scores[i]);
    bool take = (bits >> BSHIFT) >= g_thresh[b];

    unsigned int mask = __ballot_sync(0xFFFFFFFFu, take);
    if (!take) return;
    int leader = __ffs(mask) - 1;
    int lane = threadIdx.x & 31;
    unsigned int basepos = 0;
    if (lane == leader)
        basepos = atomicAdd(&g_cnt[b], (unsigned int)__popc(mask));
    basepos = __shfl_sync(mask, basepos, leader);
    unsigned int pos = basepos + __popc(mask & ((1u << lane) - 1u));
    if (pos < CAP_PB) {
        long long slot = (long long)b * CAP_PB + pos;
        g_keys64[slot] = ((unsigned long long)(unsigned int)b << 48) |
                         ((unsigned long long)bits << 16) |
                         (unsigned long long)((~s) & 0xFFFFu);
        g_vals[slot] = s;
    }
}

// start[b] = CAP - sum_{b' <= b} min(cnt[b'], CAP_PB)
__global__ void prefix_kernel() {
    int b = threadIdx.x;
    if (b >= BB) return;
    unsigned int acc = 0;
    for (int b2 = 0; b2 <= b; b2++) {
        unsigned int c = g_cnt[b2];
        if (c > CAP_PB) c = CAP_PB;
        acc += c;
    }
    g_start[b] = CAP - acc;
}

// Gather selected rows + write indices (as float).
__global__ void gather_kernel(const float* __restrict__ emb,
                              float* __restrict__ out, int k) {
    long long tid = (long long)blockIdx.x * blockDim.x + threadIdx.x;
    long long total = (long long)BB * k * (DD / 4);
    if (tid >= total) return;

    int q = (int)(tid % (DD / 4));
    long long bi = tid / (DD / 4);           // b * k + i
    int i = (int)(bi % k);
    int b = (int)(bi / k);

    unsigned int idx = g_vals_out[(long long)g_start[b] + i];

    const float4* src = (const float4*)(emb + ((long long)b * SS + idx) * DD);
    float4* dst = (float4*)(out + bi * DD);
    dst[q] = src[q];

    if (q == 0) {
        out[(long long)BB * k * DD + bi] = (float)idx;
    }
}

extern "C" void kernel_launch(void* const* d_in, const int* in_sizes, int n_in,
                              void* d_out, int out_size) {
    const float* emb = (const float*)d_in[0];
    const float* W1  = (const float*)d_in[1];
    const float* b1  = (const float*)d_in[2];
    const float* W2  = (const float*)d_in[3];
    const float* b2  = (const float*)d_in[4];
    float* out = (float*)d_out;

    // out = [sel: B*k*D][idx: B*k][scores: B*S]  (all f32)
    int k = (out_size - BB * SS) / (BB * (DD + 1));
    if (k < 1) k = 1;
    if (k > SS) k = SS;

    float* scores_out = out + (long long)BB * k * DD + (long long)BB * k;

    unsigned long long *keys_in, *keys_out;
    unsigned int *vals_in, *vals_out, *hist, *cnt;
    void* tempbuf;
    cudaGetSymbolAddress((void**)&keys_in,  g_keys64);
    cudaGetSymbolAddress((void**)&keys_out, g_keys64_out);
    cudaGetSymbolAddress((void**)&vals_in,  g_vals);
    cudaGetSymbolAddress((void**)&vals_out, g_vals_out);
    cudaGetSymbolAddress((void**)&hist,     g_hist);
    cudaGetSymbolAddress((void**)&cnt,      g_cnt);
    cudaGetSymbolAddress(&tempbuf,          g_temp);

    cudaMemsetAsync(hist, 0, BB * NBUCK * sizeof(unsigned int));
    cudaMemsetAsync(cnt,  0, BB * sizeof(unsigned int));
    cudaMemsetAsync(keys_in, 0xFF, (size_t)CAP * sizeof(unsigned long long));

    {
        long long n = (long long)BB * SS;
        score_kernel<<<(int)((n + 255) / 256), 256>>>(emb, W1, b1, W2, b2, scores_out);
    }

    hist_kernel<<<256, 256>>>(scores_out);
    scan_kernel<<<BB, 256>>>(k);
    {
        long long n = (long long)BB * SS;
        compact_kernel<<<(int)((n + 255) / 256), 256>>>(scores_out);
    }

    // Sort 53 bits: batch(5) | score(32) | ~index(16)
    size_t temp_bytes = 0;
    cub::DeviceRadixSort::SortPairsDescending(
        nullptr, temp_bytes,
        keys_in, keys_out, vals_in, vals_out,
        CAP, 0, 53, (cudaStream_t)0);
    if (temp_bytes > sizeof(g_temp)) temp_bytes = sizeof(g_temp);
    cub::DeviceRadixSort::SortPairsDescending(
        tempbuf, temp_bytes,
        keys_in, keys_out, vals_in, vals_out,
        CAP, 0, 53, (cudaStream_t)0);

    prefix_kernel<<<1, 32>>>();

    {
        long long n = (long long)BB * k * (DD / 4);
        gather_kernel<<<(int)((n + 255) / 256), 256>>>(emb, out, k);
    }
}